// round 12
// baseline (speedup 1.0000x reference)
#include <cuda_runtime.h>
#include <cuda_fp16.h>
#include <stdint.h>

#define M_DIM 2048
#define N_DIM 8192
#define K_DIM 8192

__device__ __align__(128) __half g_A[(size_t)M_DIM * K_DIM];   // 33.5 MB

// ---------------------------------------------------------------------------
// Kernel 1: x (fp32) -> fp16
// ---------------------------------------------------------------------------
__global__ void split_x_kernel(const float* __restrict__ x) {
    size_t i = ((size_t)blockIdx.x * blockDim.x + threadIdx.x) * 16;
    float4 v0 = *reinterpret_cast<const float4*>(x + i);
    float4 v1 = *reinterpret_cast<const float4*>(x + i + 4);
    float4 v2 = *reinterpret_cast<const float4*>(x + i + 8);
    float4 v3 = *reinterpret_cast<const float4*>(x + i + 12);
    __half2 h0 = __floats2half2_rn(v0.x, v0.y);
    __half2 h1 = __floats2half2_rn(v0.z, v0.w);
    __half2 h2 = __floats2half2_rn(v1.x, v1.y);
    __half2 h3 = __floats2half2_rn(v1.z, v1.w);
    __half2 h4 = __floats2half2_rn(v2.x, v2.y);
    __half2 h5 = __floats2half2_rn(v2.z, v2.w);
    __half2 h6 = __floats2half2_rn(v3.x, v3.y);
    __half2 h7 = __floats2half2_rn(v3.z, v3.w);
    uint4 o0, o1;
    o0.x = *reinterpret_cast<uint32_t*>(&h0);
    o0.y = *reinterpret_cast<uint32_t*>(&h1);
    o0.z = *reinterpret_cast<uint32_t*>(&h2);
    o0.w = *reinterpret_cast<uint32_t*>(&h3);
    o1.x = *reinterpret_cast<uint32_t*>(&h4);
    o1.y = *reinterpret_cast<uint32_t*>(&h5);
    o1.z = *reinterpret_cast<uint32_t*>(&h6);
    o1.w = *reinterpret_cast<uint32_t*>(&h7);
    *reinterpret_cast<uint4*>(&g_A[i]) = o0;
    *reinterpret_cast<uint4*>(&g_A[i + 8]) = o1;
}

// ---------------------------------------------------------------------------
// Kernel 2: GEMM with in-pipeline dequant.
// BM=BN=128, BK=64, 4 warps, occ2.
// smem: A 3-ring (cp.async fp16) | PK 2-ring (packed bytes + codebook,
// chunk-major) | BF 2 ping-pong fp16 B tiles (built by STS one iter ahead).
// ---------------------------------------------------------------------------
#define BM 128
#define BN 128
#define BK 64
#define NITER (K_DIM / BK)               // 128
#define A_ST 16384
#define PK_ST 16384
#define BF_ST 16384
#define A_OFF 0
#define PK_OFF (3 * A_ST)                // 49152
#define BF_OFF (PK_OFF + 2 * PK_ST)      // 81920
#define GEMM_SMEM (BF_OFF + 2 * BF_ST)   // 114688
#define GTHREADS 128

__device__ __forceinline__ uint32_t smem_u32(const void* p) {
    uint32_t a;
    asm("{ .reg .u64 t; cvta.to.shared.u64 t, %1; cvt.u32.u64 %0, t; }"
        : "=r"(a) : "l"(p));
    return a;
}

__device__ __forceinline__ uint32_t swz(uint32_t base, int row, int chunk) {
    return base + row * 128 + (((chunk ^ row) & 7) << 4);
}

__device__ __forceinline__ void cp16(uint32_t dst, const void* src) {
    asm volatile("cp.async.cg.shared.global [%0], [%1], 16;\n"
                 :: "r"(dst), "l"(src));
}

__device__ __forceinline__ void ldsm4(uint32_t* r, uint32_t addr) {
    asm volatile("ldmatrix.sync.aligned.m8n8.x4.shared.b16 {%0,%1,%2,%3}, [%4];"
                 : "=r"(r[0]), "=r"(r[1]), "=r"(r[2]), "=r"(r[3]) : "r"(addr));
}

__device__ __forceinline__ uint4 lds128(uint32_t a) {
    uint4 v;
    asm volatile("ld.shared.v4.u32 {%0,%1,%2,%3}, [%4];"
                 : "=r"(v.x), "=r"(v.y), "=r"(v.z), "=r"(v.w) : "r"(a));
    return v;
}

__device__ __forceinline__ void sts128(uint32_t a, uint4 v) {
    asm volatile("st.shared.v4.b32 [%0], {%1,%2,%3,%4};"
                 :: "r"(a), "r"(v.x), "r"(v.y), "r"(v.z), "r"(v.w) : "memory");
}

__device__ __forceinline__ void mma16816(float* c, const uint32_t* a,
                                         const uint32_t* b) {
    asm volatile(
        "mma.sync.aligned.m16n8k16.row.col.f32.f16.f16.f32 "
        "{%0,%1,%2,%3}, {%4,%5,%6,%7}, {%8,%9}, {%0,%1,%2,%3};\n"
        : "+f"(c[0]), "+f"(c[1]), "+f"(c[2]), "+f"(c[3])
        : "r"(a[0]), "r"(a[1]), "r"(a[2]), "r"(a[3]), "r"(b[0]), "r"(b[1]));
}

__device__ __forceinline__ uint64_t pack_tab(uint4 c) {
    return (uint64_t)__half_as_ushort(__float2half_rn(__uint_as_float(c.x)))
         | ((uint64_t)__half_as_ushort(__float2half_rn(__uint_as_float(c.y))) << 16)
         | ((uint64_t)__half_as_ushort(__float2half_rn(__uint_as_float(c.z))) << 32)
         | ((uint64_t)__half_as_ushort(__float2half_rn(__uint_as_float(c.w))) << 48);
}

__global__ void __launch_bounds__(GTHREADS, 2) gemm_kernel(
    const int* __restrict__ p, const float* __restrict__ cb,
    float* __restrict__ y) {
    extern __shared__ char smem[];
    const uint32_t sb = smem_u32(smem);
    const int tid = threadIdx.x;
    const int w = tid >> 5, lane = tid & 31;
    const int wm = (w & 1) * 64;
    const int wn = (w >> 1) * 64;
    const int bm = (blockIdx.x & 15) * BM;     // M fastest -> stripe sharing
    const int bn = (blockIdx.x >> 4) * BN;

    float acc[4][8][4];
#pragma unroll
    for (int i = 0; i < 4; i++)
#pragma unroll
        for (int j = 0; j < 8; j++)
#pragma unroll
            for (int r = 0; r < 4; r++) acc[i][j][r] = 0.0f;

    // A tile loader: 16 KB fp16, swizzled rows.
    auto load_A = [&](int slot, int chunk) {
        const int k0 = chunk * BK;
        const uint32_t abase = sb + A_OFF + slot * A_ST;
#pragma unroll
        for (int i = 0; i < 8; i++) {
            int c = tid + i * GTHREADS;
            int row = c >> 3, ch = c & 7;
            cp16(swz(abase, row, ch),
                 g_A + (size_t)(bm + row) * K_DIM + k0 + ch * 8);
        }
        asm volatile("cp.async.commit_group;" ::: "memory");
    };

    // Packed+codebook loader: chunk-major [j][row] 16B units.
    // j<6: packed ints (row has 24 ints = 6 int4); j=6,7: codebook halves.
    auto load_PK = [&](int slot, int chunk) {
        const uint32_t pbase = sb + PK_OFF + slot * PK_ST;
        const int4* pp = reinterpret_cast<const int4*>(p)
                       + (size_t)(bn + tid) * 768 + (size_t)chunk * 6;
        const float4* cc = reinterpret_cast<const float4*>(cb)
                         + (size_t)(bn + tid) * 128 + (size_t)(chunk >> 1) * 2;
#pragma unroll
        for (int j = 0; j < 6; j++)
            cp16(pbase + j * 2048 + tid * 16, pp + j);
        cp16(pbase + 6 * 2048 + tid * 16, cc);
        cp16(pbase + 7 * 2048 + tid * 16, cc + 1);
        asm volatile("cp.async.commit_group;" ::: "memory");
    };

    // Dequant one chunk: PK slot -> fp16 B tile slot (thread = row).
    auto dequant = [&](int slot) {
        const uint32_t pbase = sb + PK_OFF + slot * PK_ST;
        uint4 P0 = lds128(pbase + 0 * 2048 + tid * 16);
        uint4 P1 = lds128(pbase + 1 * 2048 + tid * 16);
        uint4 P2 = lds128(pbase + 2 * 2048 + tid * 16);
        uint4 P3 = lds128(pbase + 3 * 2048 + tid * 16);
        uint4 P4 = lds128(pbase + 4 * 2048 + tid * 16);
        uint4 P5 = lds128(pbase + 5 * 2048 + tid * 16);
        uint4 C0 = lds128(pbase + 6 * 2048 + tid * 16);
        uint4 C1 = lds128(pbase + 7 * 2048 + tid * 16);
        uint64_t t0 = pack_tab(C0);
        uint64_t t1 = pack_tab(C1);
        uint32_t W[24];
        W[0] = P0.x;  W[1] = P0.y;  W[2] = P0.z;  W[3] = P0.w;
        W[4] = P1.x;  W[5] = P1.y;  W[6] = P1.z;  W[7] = P1.w;
        W[8] = P2.x;  W[9] = P2.y;  W[10] = P2.z; W[11] = P2.w;
        W[12] = P3.x; W[13] = P3.y; W[14] = P3.z; W[15] = P3.w;
        W[16] = P4.x; W[17] = P4.y; W[18] = P4.z; W[19] = P4.w;
        W[20] = P5.x; W[21] = P5.y; W[22] = P5.z; W[23] = P5.w;
        const uint32_t bfb = sb + BF_OFF + slot * BF_ST;
#pragma unroll
        for (int g = 0; g < 8; g++) {
            unsigned bits = W[3 * g] | (W[3 * g + 1] << 8) | (W[3 * g + 2] << 16);
            uint32_t hv[8];
#pragma unroll
            for (int j = 0; j < 8; j++) {
                int idx = (bits >> (3 * j)) & 7;
                uint64_t tab = (idx & 4) ? t1 : t0;
                hv[j] = (uint32_t)(tab >> ((idx & 3) << 4)) & 0xFFFFu;
            }
            uint4 o;
            o.x = hv[0] | (hv[1] << 16);
            o.y = hv[2] | (hv[3] << 16);
            o.z = hv[4] | (hv[5] << 16);
            o.w = hv[6] | (hv[7] << 16);
            sts128(swz(bfb, tid, g), o);
        }
    };

    uint32_t ra[2][4][4], rb[2][4][4];
    auto ldfrag = [&](uint32_t abase, uint32_t bfb, int kk, int pb) {
#pragma unroll
        for (int mi = 0; mi < 4; mi++) {
            int row = wm + mi * 16 + (lane & 15);
            int ch = kk * 2 + (lane >> 4);
            ldsm4(ra[pb][mi], swz(abase, row, ch));
        }
#pragma unroll
        for (int np = 0; np < 4; np++) {
            int row = wn + np * 16 + (lane & 7) + ((lane >> 4) << 3);
            int ch = kk * 2 + ((lane >> 3) & 1);
            ldsm4(rb[pb][np], swz(bfb, row, ch));
        }
    };
    auto mma_block = [&](int pb) {
#pragma unroll
        for (int mi = 0; mi < 4; mi++)
#pragma unroll
            for (int ni = 0; ni < 8; ni++)
                mma16816(acc[mi][ni], ra[pb][mi], &rb[pb][ni >> 1][(ni & 1) * 2]);
    };

    // Prologue.  Commit order: P0, A0, P1, A1.
    load_PK(0, 0);
    load_A(0, 0);
    load_PK(1, 1);
    load_A(1, 1);
    asm volatile("cp.async.wait_group 3;" ::: "memory");   // P0 done
    dequant(0);                                            // Bf16[0] from chunk 0
    // (own-thread data; iter-0 __syncthreads orders STS vs other warps' ldsm)

    // Steady state.  Invariant at top of iter it (after wait):
    //   A(it) in slot it%3, packed(it+1) in PK slot (it+1)&1, Bf16[it&1] ready.
    auto body = [&](int it, int abuf) {
        if (it < NITER - 2)
            asm volatile("cp.async.wait_group 1;" ::: "memory");
        else
            asm volatile("cp.async.wait_group 0;" ::: "memory");
        __syncthreads();

        const uint32_t abase = sb + A_OFF + abuf * A_ST;
        const uint32_t bfb = sb + BF_OFF + (it & 1) * BF_ST;

        ldfrag(abase, bfb, 0, 0);
        if (it + 2 < NITER) load_PK((it + 2) & 1, it + 2);   // commit P first
        ldfrag(abase, bfb, 1, 1);
        if (it + 2 < NITER) load_A((abuf + 2) % 3, it + 2);  // then A

        mma_block(0);                       // kk0
        ldfrag(abase, bfb, 2, 0);
        mma_block(1);                       // kk1
        if (it + 1 < NITER) dequant((it + 1) & 1);  // build next B tile
        ldfrag(abase, bfb, 3, 1);
        mma_block(0);                       // kk2
        mma_block(1);                       // kk3
    };

    int it = 0;
#pragma unroll 1
    for (int t = 0; t < (NITER - 2) / 3; t++) {   // iters 0..125
        body(it, 0);
        body(it + 1, 1);
        body(it + 2, 2);
        it += 3;
    }
    body(126, 0);
    body(127, 1);

    // Epilogue
#pragma unroll
    for (int mi = 0; mi < 4; mi++) {
#pragma unroll
        for (int ni = 0; ni < 8; ni++) {
            int row = bm + wm + mi * 16 + (lane >> 2);
            int col = bn + wn + ni * 8 + (lane & 3) * 2;
            *reinterpret_cast<float2*>(&y[(size_t)row * N_DIM + col]) =
                make_float2(acc[mi][ni][0], acc[mi][ni][1]);
            *reinterpret_cast<float2*>(&y[(size_t)(row + 8) * N_DIM + col]) =
                make_float2(acc[mi][ni][2], acc[mi][ni][3]);
        }
    }
}

// ---------------------------------------------------------------------------
extern "C" void kernel_launch(void* const* d_in, const int* in_sizes, int n_in,
                              void* d_out, int out_size) {
    const float* x  = (const float*)d_in[0];
    const int*   p  = (const int*)d_in[1];
    const float* cb = (const float*)d_in[2];
    float* y = (float*)d_out;

    split_x_kernel<<<(M_DIM * (size_t)K_DIM / 16) / 256, 256>>>(x);

    cudaFuncSetAttribute(gemm_kernel,
                         cudaFuncAttributeMaxDynamicSharedMemorySize, GEMM_SMEM);
    gemm_kernel<<<1024, GTHREADS, GEMM_SMEM>>>(p, cb, y);
}

// round 13
// speedup vs baseline: 1.9590x; 1.9590x over previous
#include <cuda_runtime.h>
#include <cuda_fp16.h>
#include <stdint.h>

#define M_DIM 2048
#define N_DIM 8192
#define K_DIM 8192

__device__ __align__(128) __half g_A[(size_t)M_DIM * K_DIM];   // 33.5 MB
__device__ __align__(128) __half g_B[(size_t)N_DIM * K_DIM];   // 134 MB

// ---------------------------------------------------------------------------
// Kernel 1 (fused prep): blocks [0,8192) dequant W -> g_B (streaming stores),
// blocks [8192,12288) convert x -> g_A (keep in L2: GEMM re-reads A).
// ---------------------------------------------------------------------------
#define DQ_BLOCKS 8192
#define SX_BLOCKS 4096   // 2048*8192 elems / 16 per thread / 256 threads

__global__ void prep_kernel(const float* __restrict__ x,
                            const int* __restrict__ p,
                            const float* __restrict__ cb) {
    if (blockIdx.x < DQ_BLOCKS) {
        int t = blockIdx.x * blockDim.x + threadIdx.x;      // 0 .. 2097151
        const int4* p4 = reinterpret_cast<const int4*>(p) + (size_t)t * 3;
        int4 pa = p4[0], pb = p4[1], pc = p4[2];
        int by[12] = {pa.x, pa.y, pa.z, pa.w, pb.x, pb.y, pb.z, pb.w,
                      pc.x, pc.y, pc.z, pc.w};

        const float4* c4 = reinterpret_cast<const float4*>(cb)
                         + (size_t)(t >> 2) * 2;
        float4 f0 = __ldg(c4), f1 = __ldg(c4 + 1);
        uint64_t t0 = (uint64_t)__half_as_ushort(__float2half_rn(f0.x))
                    | ((uint64_t)__half_as_ushort(__float2half_rn(f0.y)) << 16)
                    | ((uint64_t)__half_as_ushort(__float2half_rn(f0.z)) << 32)
                    | ((uint64_t)__half_as_ushort(__float2half_rn(f0.w)) << 48);
        uint64_t t1 = (uint64_t)__half_as_ushort(__float2half_rn(f1.x))
                    | ((uint64_t)__half_as_ushort(__float2half_rn(f1.y)) << 16)
                    | ((uint64_t)__half_as_ushort(__float2half_rn(f1.z)) << 32)
                    | ((uint64_t)__half_as_ushort(__float2half_rn(f1.w)) << 48);

        uint4* dst = reinterpret_cast<uint4*>(g_B + (size_t)t * 32);
#pragma unroll
        for (int g = 0; g < 4; g++) {
            unsigned bits = (unsigned)by[3 * g] | ((unsigned)by[3 * g + 1] << 8)
                          | ((unsigned)by[3 * g + 2] << 16);
            uint32_t hv[8];
#pragma unroll
            for (int j = 0; j < 8; j++) {
                int idx = (bits >> (3 * j)) & 7;
                uint64_t tab = (idx & 4) ? t1 : t0;
                hv[j] = (uint32_t)(tab >> ((idx & 3) << 4)) & 0xFFFFu;
            }
            uint4 o;
            o.x = hv[0] | (hv[1] << 16);
            o.y = hv[2] | (hv[3] << 16);
            o.z = hv[4] | (hv[5] << 16);
            o.w = hv[6] | (hv[7] << 16);
            __stcs(dst + g, o);            // streaming: evict-first in L2
        }
    } else {
        size_t i = ((size_t)(blockIdx.x - DQ_BLOCKS) * blockDim.x
                    + threadIdx.x) * 16;
        float4 v0 = *reinterpret_cast<const float4*>(x + i);
        float4 v1 = *reinterpret_cast<const float4*>(x + i + 4);
        float4 v2 = *reinterpret_cast<const float4*>(x + i + 8);
        float4 v3 = *reinterpret_cast<const float4*>(x + i + 12);
        __half2 h0 = __floats2half2_rn(v0.x, v0.y);
        __half2 h1 = __floats2half2_rn(v0.z, v0.w);
        __half2 h2 = __floats2half2_rn(v1.x, v1.y);
        __half2 h3 = __floats2half2_rn(v1.z, v1.w);
        __half2 h4 = __floats2half2_rn(v2.x, v2.y);
        __half2 h5 = __floats2half2_rn(v2.z, v2.w);
        __half2 h6 = __floats2half2_rn(v3.x, v3.y);
        __half2 h7 = __floats2half2_rn(v3.z, v3.w);
        uint4 o0, o1;
        o0.x = *reinterpret_cast<uint32_t*>(&h0);
        o0.y = *reinterpret_cast<uint32_t*>(&h1);
        o0.z = *reinterpret_cast<uint32_t*>(&h2);
        o0.w = *reinterpret_cast<uint32_t*>(&h3);
        o1.x = *reinterpret_cast<uint32_t*>(&h4);
        o1.y = *reinterpret_cast<uint32_t*>(&h5);
        o1.z = *reinterpret_cast<uint32_t*>(&h6);
        o1.w = *reinterpret_cast<uint32_t*>(&h7);
        *reinterpret_cast<uint4*>(&g_A[i]) = o0;
        *reinterpret_cast<uint4*>(&g_A[i + 8]) = o1;
    }
}

// ---------------------------------------------------------------------------
// Kernel 2: GEMM (byte-identical to R10). BM=BN=128, BK=64, 4 warps, occ2,
// 3-stage ring, x3-unrolled loop, split A/B cp.async issue.
// ---------------------------------------------------------------------------
#define BM 128
#define BN 128
#define BK 64
#define NSTAGE 3
#define NITER (K_DIM / BK)               // 128
#define A_BYTES (BM * BK * 2)
#define B_BYTES (BN * BK * 2)
#define STAGE_BYTES (A_BYTES + B_BYTES)
#define GEMM_SMEM (NSTAGE * STAGE_BYTES) // 98304
#define GTHREADS 128

__device__ __forceinline__ uint32_t smem_u32(const void* p) {
    uint32_t a;
    asm("{ .reg .u64 t; cvta.to.shared.u64 t, %1; cvt.u32.u64 %0, t; }"
        : "=r"(a) : "l"(p));
    return a;
}

__device__ __forceinline__ uint32_t swz(uint32_t base, int row, int chunk) {
    return base + row * 128 + (((chunk ^ row) & 7) << 4);
}

__device__ __forceinline__ void cp16(uint32_t dst, const void* src) {
    asm volatile("cp.async.cg.shared.global [%0], [%1], 16;\n"
                 :: "r"(dst), "l"(src));
}

__device__ __forceinline__ void ldsm4(uint32_t* r, uint32_t addr) {
    asm volatile("ldmatrix.sync.aligned.m8n8.x4.shared.b16 {%0,%1,%2,%3}, [%4];"
                 : "=r"(r[0]), "=r"(r[1]), "=r"(r[2]), "=r"(r[3]) : "r"(addr));
}

__device__ __forceinline__ void mma16816(float* c, const uint32_t* a,
                                         const uint32_t* b) {
    asm volatile(
        "mma.sync.aligned.m16n8k16.row.col.f32.f16.f16.f32 "
        "{%0,%1,%2,%3}, {%4,%5,%6,%7}, {%8,%9}, {%0,%1,%2,%3};\n"
        : "+f"(c[0]), "+f"(c[1]), "+f"(c[2]), "+f"(c[3])
        : "r"(a[0]), "r"(a[1]), "r"(a[2]), "r"(a[3]), "r"(b[0]), "r"(b[1]));
}

__global__ void __launch_bounds__(GTHREADS, 2) gemm_kernel(float* __restrict__ y) {
    extern __shared__ char smem[];
    const uint32_t sb = smem_u32(smem);
    const int tid = threadIdx.x;
    const int w = tid >> 5, lane = tid & 31;
    const int wm = (w & 1) * 64;
    const int wn = (w >> 1) * 64;
    const int bm = (blockIdx.x & 15) * BM;
    const int bn = (blockIdx.x >> 4) * BN;

    float acc[4][8][4];
#pragma unroll
    for (int i = 0; i < 4; i++)
#pragma unroll
        for (int j = 0; j < 8; j++)
#pragma unroll
            for (int r = 0; r < 4; r++) acc[i][j][r] = 0.0f;

    auto load_A = [&](int buf, int chunk) {
        const int k0 = chunk * BK;
        const uint32_t abase = sb + buf * STAGE_BYTES;
#pragma unroll
        for (int i = 0; i < 8; i++) {
            int c = tid + i * GTHREADS;
            int row = c >> 3, ch = c & 7;
            cp16(swz(abase, row, ch),
                 g_A + (size_t)(bm + row) * K_DIM + k0 + ch * 8);
        }
    };
    auto load_B = [&](int buf, int chunk) {
        const int k0 = chunk * BK;
        const uint32_t bbase = sb + buf * STAGE_BYTES + A_BYTES;
#pragma unroll
        for (int i = 0; i < 8; i++) {
            int c = tid + i * GTHREADS;
            int row = c >> 3, ch = c & 7;
            cp16(swz(bbase, row, ch),
                 g_B + (size_t)(bn + row) * K_DIM + k0 + ch * 8);
        }
        asm volatile("cp.async.commit_group;" ::: "memory");
    };

    load_A(0, 0); load_B(0, 0);
    load_A(1, 1); load_B(1, 1);

    uint32_t ra[2][4][4], rb[2][4][4];

    auto ldfrag = [&](uint32_t abase, uint32_t bbase, int kk, int pb) {
#pragma unroll
        for (int mi = 0; mi < 4; mi++) {
            int row = wm + mi * 16 + (lane & 15);
            int ch = kk * 2 + (lane >> 4);
            ldsm4(ra[pb][mi], swz(abase, row, ch));
        }
#pragma unroll
        for (int np = 0; np < 4; np++) {
            int row = wn + np * 16 + (lane & 7) + ((lane >> 4) << 3);
            int ch = kk * 2 + ((lane >> 3) & 1);
            ldsm4(rb[pb][np], swz(bbase, row, ch));
        }
    };

    auto mma_block = [&](int pb) {
#pragma unroll
        for (int mi = 0; mi < 4; mi++)
#pragma unroll
            for (int ni = 0; ni < 8; ni++)
                mma16816(acc[mi][ni], ra[pb][mi], &rb[pb][ni >> 1][(ni & 1) * 2]);
    };

    auto body = [&](int it, int buf) {
        if (it < NITER - 2)
            asm volatile("cp.async.wait_group 1;" ::: "memory");
        else
            asm volatile("cp.async.wait_group 0;" ::: "memory");
        __syncthreads();

        const uint32_t abase = sb + buf * STAGE_BYTES;
        const uint32_t bbase = abase + A_BYTES;
        const int j = it + 2;
        const int jb = (buf + 2) % NSTAGE;

        ldfrag(abase, bbase, 0, 0);
        if (j < NITER) load_A(jb, j);
        ldfrag(abase, bbase, 1, 1);
        if (j < NITER) load_B(jb, j);

        mma_block(0);
        ldfrag(abase, bbase, 2, 0);
        mma_block(1);
        ldfrag(abase, bbase, 3, 1);
        mma_block(0);
        mma_block(1);
    };

    int it = 0;
#pragma unroll 1
    for (int t = 0; t < (NITER - 2) / NSTAGE; t++) {
        body(it, 0);
        body(it + 1, 1);
        body(it + 2, 2);
        it += 3;
    }
    body(126, 0);
    body(127, 1);

#pragma unroll
    for (int mi = 0; mi < 4; mi++) {
#pragma unroll
        for (int ni = 0; ni < 8; ni++) {
            int row = bm + wm + mi * 16 + (lane >> 2);
            int col = bn + wn + ni * 8 + (lane & 3) * 2;
            *reinterpret_cast<float2*>(&y[(size_t)row * N_DIM + col]) =
                make_float2(acc[mi][ni][0], acc[mi][ni][1]);
            *reinterpret_cast<float2*>(&y[(size_t)(row + 8) * N_DIM + col]) =
                make_float2(acc[mi][ni][2], acc[mi][ni][3]);
        }
    }
}

// ---------------------------------------------------------------------------
extern "C" void kernel_launch(void* const* d_in, const int* in_sizes, int n_in,
                              void* d_out, int out_size) {
    const float* x  = (const float*)d_in[0];
    const int*   p  = (const int*)d_in[1];
    const float* cb = (const float*)d_in[2];
    float* y = (float*)d_out;

    prep_kernel<<<DQ_BLOCKS + SX_BLOCKS, 256>>>(x, p, cb);

    cudaFuncSetAttribute(gemm_kernel,
                         cudaFuncAttributeMaxDynamicSharedMemorySize, GEMM_SMEM);
    gemm_kernel<<<1024, GTHREADS, GEMM_SMEM>>>(y);
}